// round 1
// baseline (speedup 1.0000x reference)
#include <cuda_runtime.h>

// Problem constants
namespace {
constexpr int D       = 256;     // d_model
constexpr int NB      = 1024;    // n_bins
constexpr int NROWS   = 32768;   // B*T
constexpr int BM      = 128;     // rows per block
constexpr int BN      = 64;      // codes per chunk
constexpr int TM      = 8;       // rows per thread
constexpr int TN      = 4;       // codes per thread
constexpr int NTHREADS = 256;    // (BM/TM)*(BN/TN)
constexpr int SMEM_Z  = BM * D;                       // 32768 floats
constexpr int SMEM_W  = D * BN;                       // 16384 floats
constexpr int SMEM_BYTES = (SMEM_Z + SMEM_W + BN) * 4;  // 196,864 B
constexpr int GATHER_BLOCKS = (NROWS * D / 4) / 256;  // 8192
}

// Scratch (device globals: no allocation allowed)
__device__ float  g_wsq[NB];
__device__ int    g_idx[NROWS];
__device__ double g_ploss[GATHER_BLOCKS];
__device__ float  g_pcnt[GATHER_BLOCKS];

// ---------------------------------------------------------------------------
// Kernel 1: ||w_j||^2 per code. grid = NB blocks of 32 threads.
// ---------------------------------------------------------------------------
__global__ void k_wsq(const float4* __restrict__ w4) {
    int code = blockIdx.x;
    int lane = threadIdx.x;
    float4 a = w4[code * (D / 4) + lane];
    float4 b = w4[code * (D / 4) + 32 + lane];
    float s = a.x * a.x + a.y * a.y + a.z * a.z + a.w * a.w
            + b.x * b.x + b.y * b.y + b.z * b.z + b.w * b.w;
#pragma unroll
    for (int off = 16; off; off >>= 1) s += __shfl_xor_sync(0xffffffffu, s, off);
    if (lane == 0) g_wsq[code] = s;
}

// ---------------------------------------------------------------------------
// Kernel 2: fused distance GEMM + argmin.
// Block: 128 rows x all 1024 codes (in 64-code chunks). z tile resident in
// smem; w chunk transposed to [k][code] in smem. Thread micro-tile 8x4.
// d = (zsq + wsq) - 2*dot, rounded exactly like the reference expression.
// ---------------------------------------------------------------------------
__global__ __launch_bounds__(NTHREADS, 1)
void k_argmin(const float4* __restrict__ z4, const float4* __restrict__ w4,
              float* __restrict__ out_idx) {
    extern __shared__ float sm[];
    float* zs   = sm;                     // [BM][D] row-major
    float* ws   = sm + SMEM_Z;            // [D][BN]  ws[k*BN + code]
    float* wsqs = sm + SMEM_Z + SMEM_W;   // [BN]

    const int tid = threadIdx.x;
    const int tx  = tid & 15;             // code group
    const int ty  = tid >> 4;             // row group
    const int rowBase = blockIdx.x * BM;

    // Load z tile: contiguous float4 copy (coalesced, conflict-free)
    {
        const float4* zsrc = z4 + (size_t)rowBase * (D / 4);
        float4* zs4 = (float4*)zs;
#pragma unroll
        for (int i = 0; i < SMEM_Z / 4 / NTHREADS; i++)
            zs4[tid + i * NTHREADS] = zsrc[tid + i * NTHREADS];
    }
    __syncthreads();

    // zsq for this thread's 8 rows: split k across tx, butterfly-sum.
    float zsqr[TM];
#pragma unroll
    for (int r = 0; r < TM; r++) {
        const float4* rp = (const float4*)&zs[(ty * TM + r) * D] + tx * 4;
        float s = 0.f;
#pragma unroll
        for (int q = 0; q < 4; q++) {
            float4 v = rp[q];
            s += v.x * v.x + v.y * v.y + v.z * v.z + v.w * v.w;
        }
        zsqr[r] = s;
    }
#pragma unroll
    for (int off = 8; off; off >>= 1)
#pragma unroll
        for (int r = 0; r < TM; r++)
            zsqr[r] += __shfl_xor_sync(0xffffffffu, zsqr[r], off);

    float mv[TM];
    int   mi[TM];
#pragma unroll
    for (int r = 0; r < TM; r++) { mv[r] = 3.4e38f; mi[r] = 0; }

    for (int cb = 0; cb < NB; cb += BN) {
        // Load w chunk transposed into ws[k][code]
#pragma unroll
        for (int i = 0; i < (BN * D / 4) / NTHREADS; i++) {   // 16
            int t    = tid + i * NTHREADS;
            int code = t >> 6;       // 0..63
            int c4   = t & 63;       // float4 column
            float4 v = w4[(size_t)(cb + code) * (D / 4) + c4];
            int k = c4 * 4;
            ws[(k + 0) * BN + code] = v.x;
            ws[(k + 1) * BN + code] = v.y;
            ws[(k + 2) * BN + code] = v.z;
            ws[(k + 3) * BN + code] = v.w;
        }
        if (tid < BN) wsqs[tid] = g_wsq[cb + tid];
        __syncthreads();

        float acc[TM][TN];
#pragma unroll
        for (int r = 0; r < TM; r++)
#pragma unroll
            for (int c = 0; c < TN; c++) acc[r][c] = 0.f;

#pragma unroll 2
        for (int k = 0; k < D; k += 4) {
            float4 a[TM];
#pragma unroll
            for (int r = 0; r < TM; r++)
                a[r] = *(const float4*)&zs[(ty * TM + r) * D + k];
            float4 b0 = *(const float4*)&ws[(k + 0) * BN + tx * TN];
            float4 b1 = *(const float4*)&ws[(k + 1) * BN + tx * TN];
            float4 b2 = *(const float4*)&ws[(k + 2) * BN + tx * TN];
            float4 b3 = *(const float4*)&ws[(k + 3) * BN + tx * TN];
#pragma unroll
            for (int r = 0; r < TM; r++) {
                float4 ar = a[r];
                acc[r][0] = fmaf(ar.x, b0.x, acc[r][0]);
                acc[r][1] = fmaf(ar.x, b0.y, acc[r][1]);
                acc[r][2] = fmaf(ar.x, b0.z, acc[r][2]);
                acc[r][3] = fmaf(ar.x, b0.w, acc[r][3]);
                acc[r][0] = fmaf(ar.y, b1.x, acc[r][0]);
                acc[r][1] = fmaf(ar.y, b1.y, acc[r][1]);
                acc[r][2] = fmaf(ar.y, b1.z, acc[r][2]);
                acc[r][3] = fmaf(ar.y, b1.w, acc[r][3]);
                acc[r][0] = fmaf(ar.z, b2.x, acc[r][0]);
                acc[r][1] = fmaf(ar.z, b2.y, acc[r][1]);
                acc[r][2] = fmaf(ar.z, b2.z, acc[r][2]);
                acc[r][3] = fmaf(ar.z, b2.w, acc[r][3]);
                acc[r][0] = fmaf(ar.w, b3.x, acc[r][0]);
                acc[r][1] = fmaf(ar.w, b3.y, acc[r][1]);
                acc[r][2] = fmaf(ar.w, b3.z, acc[r][2]);
                acc[r][3] = fmaf(ar.w, b3.w, acc[r][3]);
            }
        }
        __syncthreads();   // before ws is overwritten

        // Epilogue: d = (zsq + wsq) - 2*dot, single final rounding like ref.
        // Strict < with ascending ids preserves first-index tie-break.
#pragma unroll
        for (int c = 0; c < TN; c++) {
            int   id = cb + tx * TN + c;
            float wq = wsqs[tx * TN + c];
#pragma unroll
            for (int r = 0; r < TM; r++) {
                float t = zsqr[r] + wq;
                float v = fmaf(-2.0f, acc[r][c], t);
                if (v < mv[r]) { mv[r] = v; mi[r] = id; }
            }
        }
    }

    // Cross-tx reduction (ties -> smaller index, matching jnp.argmin)
#pragma unroll
    for (int off = 8; off; off >>= 1) {
#pragma unroll
        for (int r = 0; r < TM; r++) {
            float ov = __shfl_xor_sync(0xffffffffu, mv[r], off);
            int   oi = __shfl_xor_sync(0xffffffffu, mi[r], off);
            if (ov < mv[r] || (ov == mv[r] && oi < mi[r])) { mv[r] = ov; mi[r] = oi; }
        }
    }
    if (tx == 0) {
#pragma unroll
        for (int r = 0; r < TM; r++) {
            int row = rowBase + ty * TM + r;
            g_idx[row] = mi[r];
            if (out_idx) out_idx[row] = (float)mi[r];
        }
    }
}

// ---------------------------------------------------------------------------
// Kernel 3: gather z_q = w[idx], write it out, accumulate masked squared
// error + mask count per block (deterministic partials, no atomics).
// ---------------------------------------------------------------------------
__global__ void k_gather(const float4* __restrict__ z4,
                         const unsigned char* __restrict__ mask,
                         const float4* __restrict__ w4,
                         float4* __restrict__ out4) {
    int i   = blockIdx.x * blockDim.x + threadIdx.x;   // < NROWS*D/4
    int row = i >> 6;
    int c4  = i & 63;
    int code = g_idx[row];
    float4 wv = w4[(size_t)code * 64 + c4];
    float4 zv = z4[i];
    out4[i] = wv;

    float m  = mask[row] ? 1.f : 0.f;
    float dx = wv.x - zv.x, dy = wv.y - zv.y, dz = wv.z - zv.z, dw = wv.w - zv.w;
    float s  = m * (dx * dx + dy * dy + dz * dz + dw * dw);
    float cn = (c4 == 0) ? m : 0.f;

    // block reduction
    __shared__ float s_s[8];
    __shared__ float s_c[8];
    int lane = threadIdx.x & 31;
    int wid  = threadIdx.x >> 5;
#pragma unroll
    for (int off = 16; off; off >>= 1) {
        s  += __shfl_xor_sync(0xffffffffu, s, off);
        cn += __shfl_xor_sync(0xffffffffu, cn, off);
    }
    if (lane == 0) { s_s[wid] = s; s_c[wid] = cn; }
    __syncthreads();
    if (threadIdx.x == 0) {
        float ts = 0.f, tc = 0.f;
#pragma unroll
        for (int w = 0; w < 8; w++) { ts += s_s[w]; tc += s_c[w]; }
        g_ploss[blockIdx.x] = (double)ts;
        g_pcnt[blockIdx.x]  = tc;
    }
}

// ---------------------------------------------------------------------------
// Kernel 4: deterministic final reduction -> loss scalar.
// loss = lc + 0.25*lc with lc = S/denom (commit and codebook terms are equal)
// ---------------------------------------------------------------------------
__global__ void k_final(float* __restrict__ out_loss) {
    __shared__ double sd[256];
    __shared__ float  sc[256];
    int tid = threadIdx.x;
    double s = 0.0;
    float  c = 0.f;
    for (int i = tid; i < GATHER_BLOCKS; i += 256) { s += g_ploss[i]; c += g_pcnt[i]; }
    sd[tid] = s; sc[tid] = c;
    __syncthreads();
    for (int off = 128; off; off >>= 1) {
        if (tid < off) { sd[tid] += sd[tid + off]; sc[tid] += sc[tid + off]; }
        __syncthreads();
    }
    if (tid == 0) {
        float denom = fmaxf(sc[0] * (float)D, 1.0f);
        float lc = (float)(sd[0] / (double)denom);
        out_loss[0] = lc + 0.25f * lc;
    }
}

// ---------------------------------------------------------------------------
extern "C" void kernel_launch(void* const* d_in, const int* in_sizes, int n_in,
                              void* d_out, int out_size) {
    const float*         z    = (const float*)d_in[0];
    const unsigned char* mask = (const unsigned char*)d_in[1];
    const float*         w    = (const float*)d_in[2];
    float* out = (float*)d_out;

    // Output layout: [z_q (NROWS*D), loss (1), indices (NROWS)] as float32.
    float* out_zq   = out;
    float* out_loss = (out_size > NROWS * D) ? out + NROWS * D : nullptr;
    float* out_idx  = (out_size >= NROWS * D + 1 + NROWS) ? out + NROWS * D + 1 : nullptr;

    cudaFuncSetAttribute(k_argmin, cudaFuncAttributeMaxDynamicSharedMemorySize,
                         SMEM_BYTES);

    k_wsq<<<NB, 32>>>((const float4*)w);
    k_argmin<<<NROWS / BM, NTHREADS, SMEM_BYTES>>>((const float4*)z,
                                                   (const float4*)w, out_idx);
    k_gather<<<GATHER_BLOCKS, 256>>>((const float4*)z, mask, (const float4*)w,
                                     (float4*)out_zq);
    if (out_loss) k_final<<<1, 256>>>(out_loss);
}

// round 8
// speedup vs baseline: 1.4722x; 1.4722x over previous
#include <cuda_runtime.h>
#include <cstdint>

// ============================ constants ====================================
namespace {
constexpr int D = 256, NB = 1024, NROWS = 32768;
constexpr int BM = 128;            // rows per CTA
constexpr int BN = 256;            // codes per n-chunk
constexpr int KC = 32;             // k per chunk
constexpr int TOTCH = 32;          // 4 n-chunks * 8 k-chunks
constexpr int NTHREADS = 256;
constexpr int GATHER_BLOCKS = (NROWS * D / 4) / 256;   // 8192
constexpr int CMAX = 32;           // candidate slots per row
constexpr float DELTA = 1e-3f;     // filter margin (>> 3xTF32 error bound)

// smem byte layout (k_argmin_mma)
constexpr uint32_t A_MAT   = 128 * 36 * 4;   // 18432 (pad 36 floats)
constexpr uint32_t B_MAT   = 256 * 36 * 4;   // 36864
constexpr uint32_t A_BASE  = 0;              // buf*(2*A_MAT): {Ahi,Alo}
constexpr uint32_t B_BASE  = 4 * A_MAT;      // 73728, buf*(2*B_MAT): {Bhi,Blo}
constexpr uint32_t WSQ_OFF = B_BASE + 4 * B_MAT;   // 221184 (4 KB)
constexpr uint32_t EXCH_OFF = WSQ_OFF + NB * 4;     // 225280 (2KB mv + 512B rowmin)
constexpr uint32_t SMEM_TOTAL = EXCH_OFF + 2560;    // 227840 B (< 232448 cap)
}

// ============================ scratch globals ==============================
__device__ float4 g_zhi4[NROWS * D / 4];
__device__ float4 g_zlo4[NROWS * D / 4];
__device__ float4 g_whi4[NB * D / 4];
__device__ float4 g_wlo4[NB * D / 4];
__device__ float  g_wsq[NB];
__device__ int    g_idx[NROWS];
__device__ unsigned short g_cand[NROWS * CMAX];
__device__ int    g_ccnt[NROWS];
__device__ double g_ploss[GATHER_BLOCKS];
__device__ float  g_pcnt[GATHER_BLOCKS];

// ============================ PTX helpers ==================================
__device__ __forceinline__ uint32_t smem_u32(const void* p) {
    uint32_t a;
    asm("{ .reg .u64 t; cvta.to.shared.u64 t, %1; cvt.u32.u64 %0, t; }"
        : "=r"(a) : "l"(p));
    return a;
}
#define CP16(sdst, gsrc) \
    asm volatile("cp.async.cg.shared.global [%0], [%1], 16;" \
                 :: "r"(sdst), "l"(gsrc) : "memory")
#define CP_COMMIT() asm volatile("cp.async.commit_group;" ::: "memory")
#define CP_WAIT(N)  asm volatile("cp.async.wait_group %0;" :: "n"(N) : "memory")

__device__ __forceinline__ void mma8(float* cc,
                                     uint32_t a0, uint32_t a1, uint32_t a2, uint32_t a3,
                                     uint32_t b0, uint32_t b1) {
    asm volatile(
        "mma.sync.aligned.m16n8k8.row.col.f32.tf32.tf32.f32 "
        "{%0,%1,%2,%3}, {%4,%5,%6,%7}, {%8,%9}, {%0,%1,%2,%3};"
        : "+f"(cc[0]), "+f"(cc[1]), "+f"(cc[2]), "+f"(cc[3])
        : "r"(a0), "r"(a1), "r"(a2), "r"(a3), "r"(b0), "r"(b1));
}

__device__ __forceinline__ uint32_t f2u(float f) { return __float_as_uint(f); }

__device__ __forceinline__ void split1(float f, float& h, float& l) {
    uint32_t u;
    asm("cvt.rna.tf32.f32 %0, %1;" : "=r"(u) : "f"(f));
    h = __uint_as_float(u);
    float lf = f - h;
    asm("cvt.rna.tf32.f32 %0, %1;" : "=r"(u) : "f"(lf));
    l = __uint_as_float(u);
}

// ---------------------------------------------------------------------------
// Kernel 0: tf32 hi/lo pre-split of z and w; zero candidate counters.
// ---------------------------------------------------------------------------
__global__ void k_split(const float4* __restrict__ z4,
                        const float4* __restrict__ w4) {
    constexpr int NZ4 = NROWS * D / 4;
    constexpr int NW4 = NB * D / 4;
    int i = blockIdx.x * blockDim.x + threadIdx.x;
    if (i < NROWS) g_ccnt[i] = 0;
    if (i < NZ4) {
        float4 v = z4[i], h, l;
        split1(v.x, h.x, l.x); split1(v.y, h.y, l.y);
        split1(v.z, h.z, l.z); split1(v.w, h.w, l.w);
        g_zhi4[i] = h; g_zlo4[i] = l;
    } else if (i < NZ4 + NW4) {
        int j = i - NZ4;
        float4 v = w4[j], h, l;
        split1(v.x, h.x, l.x); split1(v.y, h.y, l.y);
        split1(v.z, h.z, l.z); split1(v.w, h.w, l.w);
        g_whi4[j] = h; g_wlo4[j] = l;
    }
}

// ---------------------------------------------------------------------------
// Kernel 1: ||w_j||^2 per code (round-1 identical rounding).
// ---------------------------------------------------------------------------
__global__ void k_wsq(const float4* __restrict__ w4) {
    int code = blockIdx.x;
    int lane = threadIdx.x;
    float4 a = w4[code * (D / 4) + lane];
    float4 b = w4[code * (D / 4) + 32 + lane];
    float s = a.x * a.x + a.y * a.y + a.z * a.z + a.w * a.w
            + b.x * b.x + b.y * b.y + b.z * b.z + b.w * b.w;
#pragma unroll
    for (int off = 16; off; off >>= 1) s += __shfl_xor_sync(0xffffffffu, s, off);
    if (lane == 0) g_wsq[code] = s;
}

// ---------------------------------------------------------------------------
// Kernel 2: 3xTF32 mma.sync GEMM -> per-row candidate filter.
// v_approx = fmaf(-2, acc, wsq)  (zsq is row-constant: dropped, cancels).
// Codes with v_approx <= running_rowmin + DELTA are appended to g_cand.
// ---------------------------------------------------------------------------
__device__ __forceinline__ void issue_chunk(int tid, int rowBase, int t,
                                            uint32_t sb) {
    const int n = t >> 3, kc = t & 7, buf = t & 1;
    const uint32_t aHi = sb + A_BASE + (uint32_t)buf * (2 * A_MAT);
    const uint32_t aLo = aHi + A_MAT;
    const uint32_t bHi = sb + B_BASE + (uint32_t)buf * (2 * B_MAT);
    const uint32_t bLo = bHi + B_MAT;
    const char* zh = (const char*)g_zhi4;
    const char* zl = (const char*)g_zlo4;
    const char* wh = (const char*)g_whi4;
    const char* wl = (const char*)g_wlo4;
#pragma unroll
    for (int i = 0; i < 4; i++) {           // A: 128 rows x 32 k (hi+lo)
        int idx = tid + i * 256;
        int row = idx >> 3, seg = idx & 7;
        size_t go = ((size_t)(rowBase + row) * D + kc * KC + seg * 4) * 4;
        uint32_t so = (uint32_t)(row * 144 + seg * 16);
        CP16(aHi + so, zh + go);
        CP16(aLo + so, zl + go);
    }
#pragma unroll
    for (int i = 0; i < 8; i++) {           // B: 256 codes x 32 k (hi+lo)
        int idx = tid + i * 256;
        int row = idx >> 3, seg = idx & 7;
        size_t go = ((size_t)(n * BN + row) * D + kc * KC + seg * 4) * 4;
        uint32_t so = (uint32_t)(row * 144 + seg * 16);
        CP16(bHi + so, wh + go);
        CP16(bLo + so, wl + go);
    }
}

__global__ __launch_bounds__(NTHREADS, 1)
void k_argmin_mma() {
    extern __shared__ char smem[];
    const uint32_t sb = smem_u32(smem);
    const int tid  = threadIdx.x;
    const int lane = tid & 31;
    const int wid  = tid >> 5;
    const int wm   = wid >> 2;       // 0..1  (M 64-half)
    const int wn   = wid & 3;        // 0..3  (N 64-quarter)
    const int g    = lane >> 2;      // 0..7
    const int c    = lane & 3;       // 0..3
    const int rowBase = blockIdx.x * BM;

    issue_chunk(tid, rowBase, 0, sb);
    CP_COMMIT();

    float* wsq_s = (float*)(smem + WSQ_OFF);
#pragma unroll
    for (int i = tid; i < NB; i += NTHREADS) wsq_s[i] = g_wsq[i];
    __syncthreads();

    // lane-constant smem float-indices
    int arow[4], bcol[8];
#pragma unroll
    for (int mt = 0; mt < 4; mt++) arow[mt] = (wm * 64 + mt * 16 + g) * 36 + c;
#pragma unroll
    for (int nt = 0; nt < 8; nt++) bcol[nt] = (wn * 64 + nt * 8 + g) * 36 + c;

    float mv = 3.4e38f;              // running row min (tid<128 rows)
    float acc[4][8][4];
#pragma unroll
    for (int a = 0; a < 4; a++)
#pragma unroll
        for (int b = 0; b < 8; b++)
#pragma unroll
            for (int q = 0; q < 4; q++) acc[a][b][q] = 0.f;

    for (int t = 0; t < TOTCH; t++) {
        if (t < TOTCH - 1) {
            issue_chunk(tid, rowBase, t + 1, sb);
            CP_COMMIT();
            CP_WAIT(1);
        } else {
            CP_WAIT(0);
        }
        __syncthreads();

        // ---- compute chunk t from buf t&1 ----
        {
            const int buf = t & 1;
            const float* Ah = (const float*)(smem + A_BASE + buf * (2 * A_MAT));
            const float* Al = (const float*)((const char*)Ah + A_MAT);
            const float* Bh = (const float*)(smem + B_BASE + buf * (2 * B_MAT));
            const float* Bl = (const float*)((const char*)Bh + B_MAT);
#pragma unroll
            for (int ks = 0; ks < 4; ks++) {
                const int kof = ks * 8;
                uint32_t bh0[8], bh1[8], bl0[8], bl1[8];
#pragma unroll
                for (int nt = 0; nt < 8; nt++) {
                    bh0[nt] = f2u(Bh[bcol[nt] + kof]);
                    bh1[nt] = f2u(Bh[bcol[nt] + kof + 4]);
                    bl0[nt] = f2u(Bl[bcol[nt] + kof]);
                    bl1[nt] = f2u(Bl[bcol[nt] + kof + 4]);
                }
#pragma unroll
                for (int mt = 0; mt < 4; mt++) {
                    const int ao = arow[mt] + kof;
                    uint32_t ah0 = f2u(Ah[ao]),       ah1 = f2u(Ah[ao + 288]);
                    uint32_t ah2 = f2u(Ah[ao + 4]),   ah3 = f2u(Ah[ao + 292]);
                    uint32_t al0 = f2u(Al[ao]),       al1 = f2u(Al[ao + 288]);
                    uint32_t al2 = f2u(Al[ao + 4]),   al3 = f2u(Al[ao + 292]);
#pragma unroll
                    for (int nt = 0; nt < 8; nt++) {
                        mma8(acc[mt][nt], ah0, ah1, ah2, ah3, bh0[nt], bh1[nt]);
                        mma8(acc[mt][nt], ah0, ah1, ah2, ah3, bl0[nt], bl1[nt]);
                        mma8(acc[mt][nt], al0, al1, al2, al3, bh0[nt], bh1[nt]);
                    }
                }
            }
        }
        __syncthreads();

        // ---- n-chunk epilogue: row min + candidate append ----
        if ((t & 7) == 7) {
            const int n = t >> 3;
            float* exch_mv  = (float*)(smem + EXCH_OFF);
            float* rowmin_s = (float*)(smem + EXCH_OFF + 2048);

            float rmv[8];
#pragma unroll
            for (int mt = 0; mt < 4; mt++)
#pragma unroll
                for (int h = 0; h < 2; h++) {
                    float bv = 3.4e38f;
#pragma unroll
                    for (int nt = 0; nt < 8; nt++)
#pragma unroll
                        for (int q = 0; q < 2; q++) {
                            int code = n * BN + wn * 64 + nt * 8 + 2 * c + q;
                            float v = fmaf(-2.0f, acc[mt][nt][h * 2 + q],
                                           wsq_s[code]);
                            bv = fminf(bv, v);
                        }
                    rmv[mt * 2 + h] = bv;
                }
#pragma unroll
            for (int off = 1; off <= 2; off <<= 1)
#pragma unroll
                for (int rr = 0; rr < 8; rr++)
                    rmv[rr] = fminf(rmv[rr],
                                    __shfl_xor_sync(0xffffffffu, rmv[rr], off));
            if (c == 0) {
#pragma unroll
                for (int mt = 0; mt < 4; mt++)
#pragma unroll
                    for (int h = 0; h < 2; h++) {
                        int ctaRow = wm * 64 + mt * 16 + h * 8 + g;
                        exch_mv[ctaRow * 4 + wn] = rmv[mt * 2 + h];
                    }
            }
            __syncthreads();
            if (tid < BM) {
#pragma unroll
                for (int q = 0; q < 4; q++) mv = fminf(mv, exch_mv[tid * 4 + q]);
                rowmin_s[tid] = mv;
            }
            __syncthreads();

            // re-walk accumulators, append candidates
#pragma unroll
            for (int mt = 0; mt < 4; mt++)
#pragma unroll
                for (int h = 0; h < 2; h++) {
                    const int ctaRow = wm * 64 + mt * 16 + h * 8 + g;
                    const float thr = rowmin_s[ctaRow] + DELTA;
                    const int row = rowBase + ctaRow;
#pragma unroll
                    for (int nt = 0; nt < 8; nt++)
#pragma unroll
                        for (int q = 0; q < 2; q++) {
                            int code = n * BN + wn * 64 + nt * 8 + 2 * c + q;
                            float v = fmaf(-2.0f, acc[mt][nt][h * 2 + q],
                                           wsq_s[code]);
                            if (v <= thr) {
                                int pos = atomicAdd(&g_ccnt[row], 1);
                                if (pos < CMAX)
                                    g_cand[row * CMAX + pos] =
                                        (unsigned short)code;
                            }
                        }
                }
            __syncthreads();
#pragma unroll
            for (int a = 0; a < 4; a++)
#pragma unroll
                for (int b = 0; b < 8; b++)
#pragma unroll
                    for (int q = 0; q < 4; q++) acc[a][b][q] = 0.f;
        }
    }
}

// ---------------------------------------------------------------------------
// Kernel 2b: exact rescore of candidates, bit-identical to round-1 arithmetic.
// One thread per row. zsq = R1's group/tree recipe; dot = ascending-k FMA
// chain (R1's order); v = fmaf(-2, acc, zsq + wsq); lex-min (v, idx).
// ---------------------------------------------------------------------------
__global__ void k_rescore(const float4* __restrict__ z4,
                          const float4* __restrict__ w4,
                          float* __restrict__ out_idx) {
    int row = blockIdx.x * blockDim.x + threadIdx.x;
    if (row >= NROWS) return;
    const float4* zp = z4 + (size_t)row * (D / 4);

    // zsq: 16 groups of 16 elements, then R1's pairwise tree
    float part[16];
#pragma unroll
    for (int q = 0; q < 16; q++) {
        float s = 0.f;
#pragma unroll
        for (int u = 0; u < 4; u++) {
            float4 v = zp[q * 4 + u];
            s += v.x * v.x + v.y * v.y + v.z * v.z + v.w * v.w;
        }
        part[q] = s;
    }
#pragma unroll
    for (int off = 8; off; off >>= 1)
#pragma unroll
        for (int q = 0; q < 8; q++)
            if (q < off) part[q] += part[q + off];
    const float zsq = part[0];

    const int cnt = g_ccnt[row];
    float mv = 3.4e38f;
    int   mi = 0;
    const int ncand = (cnt <= CMAX) ? cnt : NB;
    for (int j = 0; j < ncand; j++) {
        const int code = (cnt <= CMAX) ? (int)g_cand[row * CMAX + j] : j;
        const float4* wp = w4 + (size_t)code * (D / 4);
        float acc = 0.f;
#pragma unroll 8
        for (int k4 = 0; k4 < D / 4; k4++) {
            float4 zv = zp[k4];
            float4 wv = wp[k4];
            acc = fmaf(zv.x, wv.x, acc);
            acc = fmaf(zv.y, wv.y, acc);
            acc = fmaf(zv.z, wv.z, acc);
            acc = fmaf(zv.w, wv.w, acc);
        }
        float t = zsq + g_wsq[code];
        float v = fmaf(-2.0f, acc, t);
        if (v < mv || (v == mv && code < mi)) { mv = v; mi = code; }
    }
    g_idx[row] = mi;
    if (out_idx) out_idx[row] = (float)mi;
}

// ---------------------------------------------------------------------------
// Kernel 3: gather z_q = w[idx] + masked loss partials (round-1 identical).
// ---------------------------------------------------------------------------
__global__ void k_gather(const float4* __restrict__ z4,
                         const unsigned char* __restrict__ mask,
                         const float4* __restrict__ w4,
                         float4* __restrict__ out4) {
    int i   = blockIdx.x * blockDim.x + threadIdx.x;
    int row = i >> 6;
    int c4  = i & 63;
    int code = g_idx[row];
    float4 wv = w4[(size_t)code * 64 + c4];
    float4 zv = z4[i];
    out4[i] = wv;

    float m  = mask[row] ? 1.f : 0.f;
    float dx = wv.x - zv.x, dy = wv.y - zv.y, dz = wv.z - zv.z, dw = wv.w - zv.w;
    float s  = m * (dx * dx + dy * dy + dz * dz + dw * dw);
    float cn = (c4 == 0) ? m : 0.f;

    __shared__ float s_s[8];
    __shared__ float s_c[8];
    int lane = threadIdx.x & 31;
    int wd   = threadIdx.x >> 5;
#pragma unroll
    for (int off = 16; off; off >>= 1) {
        s  += __shfl_xor_sync(0xffffffffu, s, off);
        cn += __shfl_xor_sync(0xffffffffu, cn, off);
    }
    if (lane == 0) { s_s[wd] = s; s_c[wd] = cn; }
    __syncthreads();
    if (threadIdx.x == 0) {
        float ts = 0.f, tc = 0.f;
#pragma unroll
        for (int w = 0; w < 8; w++) { ts += s_s[w]; tc += s_c[w]; }
        g_ploss[blockIdx.x] = (double)ts;
        g_pcnt[blockIdx.x]  = tc;
    }
}

// ---------------------------------------------------------------------------
// Kernel 4: final reduction -> loss scalar.
// ---------------------------------------------------------------------------
__global__ void k_final(float* __restrict__ out_loss) {
    __shared__ double sd[1024];
    __shared__ float  sc[1024];
    int tid = threadIdx.x;
    double s = 0.0;
    float  c = 0.f;
    for (int i = tid; i < GATHER_BLOCKS; i += 1024) { s += g_ploss[i]; c += g_pcnt[i]; }
    sd[tid] = s; sc[tid] = c;
    __syncthreads();
    for (int off = 512; off; off >>= 1) {
        if (tid < off) { sd[tid] += sd[tid + off]; sc[tid] += sc[tid + off]; }
        __syncthreads();
    }
    if (tid == 0) {
        float denom = fmaxf(sc[0] * (float)D, 1.0f);
        float lc = (float)(sd[0] / (double)denom);
        out_loss[0] = lc + 0.25f * lc;
    }
}

// ---------------------------------------------------------------------------
extern "C" void kernel_launch(void* const* d_in, const int* in_sizes, int n_in,
                              void* d_out, int out_size) {
    const float*         z    = (const float*)d_in[0];
    const unsigned char* mask = (const unsigned char*)d_in[1];
    const float*         w    = (const float*)d_in[2];
    float* out = (float*)d_out;

    float* out_zq   = out;
    float* out_loss = (out_size > NROWS * D) ? out + NROWS * D : nullptr;
    float* out_idx  = (out_size >= NROWS * D + 1 + NROWS) ? out + NROWS * D + 1 : nullptr;

    cudaFuncSetAttribute(k_argmin_mma,
                         cudaFuncAttributeMaxDynamicSharedMemorySize, SMEM_TOTAL);

    constexpr int NSPLIT = NROWS * D / 4 + NB * D / 4;
    k_split<<<(NSPLIT + 255) / 256, 256>>>((const float4*)z, (const float4*)w);
    k_wsq<<<NB, 32>>>((const float4*)w);
    k_argmin_mma<<<NROWS / BM, NTHREADS, SMEM_TOTAL>>>();
    k_rescore<<<NROWS / 256, 256>>>((const float4*)z, (const float4*)w, out_idx);
    k_gather<<<GATHER_BLOCKS, 256>>>((const float4*)z, mask, (const float4*)w,
                                     (float4*)out_zq);
    if (out_loss) k_final<<<1, 1024>>>(out_loss);
}